// round 7
// baseline (speedup 1.0000x reference)
#include <cuda_runtime.h>

#define POOL   7
#define NPIX   49
#define BATCH  2
#define NBOX   1000
#define CCH    256
#define C4     (CCH / 4)
#define ITEMS  (NPIX * C4)      // 3136 float4 items per box
#define TPB    448              // 7 * 64 ; ITEMS = 7 * TPB exactly

// inverse permutation: g_inv[b*NBOX + rank] = global box id
__device__ int g_inv[BATCH * NBOX];

// ---------------------------------------------------------------------------
// Kernel 1: stable argsort via 4-way counting-sort prefix scan.
// One block per batch (1024 threads >= NBOX). Writes the INVERSE permutation
// so the roi kernel can be scheduled in sorted (level-clustered) order.
// ---------------------------------------------------------------------------
__global__ void slot_kernel(const int* __restrict__ level) {
    const int b = blockIdx.x, tid = threadIdx.x;
    const int warp = tid >> 5, lane = tid & 31;
    __shared__ unsigned long long warpBase[32];
    __shared__ unsigned long long levelBase;
    __shared__ unsigned long long warpTot[32];

    const int lv = (tid < NBOX) ? level[b * NBOX + tid] : 0;   // 1..4 (0 = pad)
    const unsigned p = (lv >= 1) ? (1u << (8 * (lv - 1))) : 0u;

    unsigned incl = p;
    #pragma unroll
    for (int d = 1; d < 32; d <<= 1) {
        unsigned n = __shfl_up_sync(0xffffffffu, incl, d);
        if (lane >= d) incl += n;
    }
    if (lane == 31) {
        unsigned long long t = 0;
        t |= (unsigned long long)( incl        & 0xFF);
        t |= (unsigned long long)((incl >>  8) & 0xFF) << 16;
        t |= (unsigned long long)((incl >> 16) & 0xFF) << 32;
        t |= (unsigned long long)((incl >> 24) & 0xFF) << 48;
        warpTot[warp] = t;
    }
    __syncthreads();
    if (tid == 0) {
        unsigned long long run = 0;
        #pragma unroll
        for (int w = 0; w < 32; ++w) { warpBase[w] = run; run += warpTot[w]; }
        const unsigned t1 =  run        & 0xFFFF;
        const unsigned t2 = (run >> 16) & 0xFFFF;
        const unsigned t3 = (run >> 32) & 0xFFFF;
        unsigned long long lb = 0;
        lb |= (unsigned long long)(t1)           << 16;
        lb |= (unsigned long long)(t1 + t2)      << 32;
        lb |= (unsigned long long)(t1 + t2 + t3) << 48;
        levelBase = lb;
    }
    __syncthreads();
    if (tid < NBOX) {
        const int f = lv - 1;
        const unsigned myExcl = ((incl - p) >> (8 * f)) & 0xFF;
        const unsigned wb   = (unsigned)((warpBase[warp] >> (16 * f)) & 0xFFFF);
        const unsigned base = (unsigned)((levelBase      >> (16 * f)) & 0xFFFF);
        g_inv[b * NBOX + (int)(base + wb + myExcl)] = b * NBOX + tid;
    }
}

// ---------------------------------------------------------------------------
// Kernel 2: one block per OUTPUT rank (level-clustered schedule).
//   box = g_inv[blockIdx]  -> concurrent blocks share a level -> L2 reuse.
//   output base = blockIdx * ITEMS (already permuted).
// 448 threads, exactly 7 items/thread, software-pipelined (prefetch next
// pixel's 4 corner loads while computing the current one).
// ---------------------------------------------------------------------------
__global__ __launch_bounds__(TPB) void roi_kernel(
    const float* __restrict__ boxes,
    const float* __restrict__ fm0,
    const float* __restrict__ fm1,
    const float* __restrict__ fm2,
    const float* __restrict__ fm3,
    const int*   __restrict__ level,
    float*       __restrict__ out)
{
    __shared__ int4   sIdx[NPIX];   // corner base indices (float4 units)
    __shared__ float4 sW[NPIX];     // {wy, wx, validf, -}

    const int rank = blockIdx.x;             // output position
    const int box  = g_inv[rank];            // input box (global id)
    const int b    = (box >= NBOX) ? 1 : 0;
    const int tid  = threadIdx.x;

    const int lv = __ldg(level + box) - 1;   // 0..3
    const float* fm; int S;
    switch (lv) {
        case 0:  fm = fm0; S = 256; break;
        case 1:  fm = fm1; S = 128; break;
        case 2:  fm = fm2; S = 64;  break;
        default: fm = fm3; S = 32;  break;
    }

    if (tid < NPIX) {
        const int py = tid / POOL;
        const int px = tid - py * POOL;
        const float sm1 = (float)(S - 1);

        const float y1 = __ldg(boxes + box * 4 + 0);
        const float x1 = __ldg(boxes + box * 4 + 1);
        const float y2 = __ldg(boxes + box * 4 + 2);
        const float x2 = __ldg(boxes + box * 4 + 3);

        const float in_y = y1 * sm1 + (float)py * ((y2 - y1) * sm1 / 6.0f);
        const float in_x = x1 * sm1 + (float)px * ((x2 - x1) * sm1 / 6.0f);

        const bool valid = (in_y >= 0.0f) && (in_y <= sm1) &&
                           (in_x >= 0.0f) && (in_x <= sm1);

        const float fy = floorf(in_y);
        const float fx = floorf(in_x);
        const int ty = (int)fminf(fmaxf(fy, 0.0f), sm1);
        const int by = min(ty + 1, S - 1);
        const int lx = (int)fminf(fmaxf(fx, 0.0f), sm1);
        const int rx = min(lx + 1, S - 1);

        const int rowT = (b * S + ty) * S;
        const int rowB = (b * S + by) * S;
        sIdx[tid] = make_int4((rowT + lx) * C4, (rowT + rx) * C4,
                              (rowB + lx) * C4, (rowB + rx) * C4);
        sW[tid] = make_float4(in_y - fy, in_x - fx, valid ? 1.0f : 0.0f, 0.0f);
    }
    __syncthreads();

    const float4* f4 = (const float4*)fm;
    float4* o4 = (float4*)out + (size_t)rank * ITEMS;

    const int c = tid & (C4 - 1);   // loop-invariant channel group
    const int q = tid >> 6;         // 0..6

    // --- software pipeline: prefetch pixel for k+1 while computing k ---
    int4   idC = sIdx[q];
    float4 wC  = sW[q];
    float4 tlC = __ldg(f4 + idC.x + c);
    float4 trC = __ldg(f4 + idC.y + c);
    float4 blC = __ldg(f4 + idC.z + c);
    float4 brC = __ldg(f4 + idC.w + c);

    #pragma unroll
    for (int k = 0; k < 7; ++k) {
        int4 idN; float4 wN, tlN, trN, blN, brN;
        if (k < 6) {
            const int pN = 7 * (k + 1) + q;
            idN = sIdx[pN];
            wN  = sW[pN];
            tlN = __ldg(f4 + idN.x + c);
            trN = __ldg(f4 + idN.y + c);
            blN = __ldg(f4 + idN.z + c);
            brN = __ldg(f4 + idN.w + c);
        }

        float4 r;
        {
            float top, bot;
            top = tlC.x + (trC.x - tlC.x) * wC.y; bot = blC.x + (brC.x - blC.x) * wC.y;
            r.x = (top + (bot - top) * wC.x) * wC.z;
            top = tlC.y + (trC.y - tlC.y) * wC.y; bot = blC.y + (brC.y - blC.y) * wC.y;
            r.y = (top + (bot - top) * wC.x) * wC.z;
            top = tlC.z + (trC.z - tlC.z) * wC.y; bot = blC.z + (brC.z - blC.z) * wC.y;
            r.z = (top + (bot - top) * wC.x) * wC.z;
            top = tlC.w + (trC.w - tlC.w) * wC.y; bot = blC.w + (brC.w - blC.w) * wC.y;
            r.w = (top + (bot - top) * wC.x) * wC.z;
        }
        o4[k * TPB + tid] = r;

        if (k < 6) {
            idC = idN; wC = wN;
            tlC = tlN; trC = trN; blC = blN; brC = brN;
        }
    }
}

// ---------------------------------------------------------------------------
// Launch
// ---------------------------------------------------------------------------
extern "C" void kernel_launch(void* const* d_in, const int* in_sizes, int n_in,
                              void* d_out, int out_size) {
    const float* boxes = (const float*)d_in[0];
    const float* fm0   = (const float*)d_in[1];
    const float* fm1   = (const float*)d_in[2];
    const float* fm2   = (const float*)d_in[3];
    const float* fm3   = (const float*)d_in[4];
    const int*   level = (const int*)  d_in[5];
    float*       out   = (float*)d_out;

    slot_kernel<<<BATCH, 1024>>>(level);
    roi_kernel<<<BATCH * NBOX, TPB>>>(boxes, fm0, fm1, fm2, fm3, level, out);
}

// round 8
// speedup vs baseline: 1.1705x; 1.1705x over previous
#include <cuda_runtime.h>

#define POOL   7
#define NPIX   49
#define BATCH  2
#define NBOX   1000
#define CCH    256
#define C4     (CCH / 4)
#define ITEMS  (NPIX * C4)      // 3136 float4 items per box

// ---------------------------------------------------------------------------
// Fused kernel: one block per box (input order -> no indirection at start).
//  - slot (stable-sort rank) computed in-block by predicate count.
//  - 49 threads precompute per-pixel corner indices + weights into shared.
//  - flat loop: 6 x 512 items + 64-item tail, fully unrolled.
//  - __launch_bounds__(512, 4): force 32 regs -> 4 blocks/SM -> 100% occ.
//  - __stcs output stores: evict-first, keep L2 for feature-map reads.
// ---------------------------------------------------------------------------
__global__ __launch_bounds__(512, 4) void roi_kernel(
    const float* __restrict__ boxes,
    const float* __restrict__ fm0,
    const float* __restrict__ fm1,
    const float* __restrict__ fm2,
    const float* __restrict__ fm3,
    const int*   __restrict__ level,
    float*       __restrict__ out)
{
    __shared__ int4   sIdx[NPIX];   // corner base indices (float4 units)
    __shared__ float4 sW[NPIX];     // {wy, wx, validf, -}
    __shared__ int    sRed[16];
    __shared__ int    sSlot;

    const int box = blockIdx.x;              // 0..1999
    const int b   = (box >= NBOX) ? 1 : 0;
    const int ii  = box - b * NBOX;          // index within batch
    const int tid = threadIdx.x;
    const int warp = tid >> 5, lane = tid & 31;

    const int myLv = __ldg(level + box);     // 1..4

    const float* fm; int S;
    switch (myLv - 1) {
        case 0:  fm = fm0; S = 256; break;
        case 1:  fm = fm1; S = 128; break;
        case 2:  fm = fm2; S = 64;  break;
        default: fm = fm3; S = 32;  break;
    }

    // ---- slot: predicate count over this batch's 1000 levels ----
    {
        const int* lvArr = level + b * NBOX;
        int cnt = 0;
        #pragma unroll
        for (int j = tid; j < NBOX; j += 512) {
            const int lj = __ldg(lvArr + j);
            cnt += (lj < myLv) || (lj == myLv && j < ii);
        }
        #pragma unroll
        for (int d = 16; d; d >>= 1) cnt += __shfl_xor_sync(0xffffffffu, cnt, d);
        if (lane == 0) sRed[warp] = cnt;
    }

    // ---- per-pixel params (threads 0..48) ----
    if (tid < NPIX) {
        const int py = tid / POOL;
        const int px = tid - py * POOL;
        const float sm1 = (float)(S - 1);

        const float y1 = __ldg(boxes + box * 4 + 0);
        const float x1 = __ldg(boxes + box * 4 + 1);
        const float y2 = __ldg(boxes + box * 4 + 2);
        const float x2 = __ldg(boxes + box * 4 + 3);

        const float in_y = y1 * sm1 + (float)py * ((y2 - y1) * sm1 / 6.0f);
        const float in_x = x1 * sm1 + (float)px * ((x2 - x1) * sm1 / 6.0f);

        const bool valid = (in_y >= 0.0f) && (in_y <= sm1) &&
                           (in_x >= 0.0f) && (in_x <= sm1);

        const float fy = floorf(in_y);
        const float fx = floorf(in_x);
        const int ty = (int)fminf(fmaxf(fy, 0.0f), sm1);
        const int by = min(ty + 1, S - 1);
        const int lx = (int)fminf(fmaxf(fx, 0.0f), sm1);
        const int rx = min(lx + 1, S - 1);

        const int rowT = (b * S + ty) * S;
        const int rowB = (b * S + by) * S;
        sIdx[tid] = make_int4((rowT + lx) * C4, (rowT + rx) * C4,
                              (rowB + lx) * C4, (rowB + rx) * C4);
        sW[tid] = make_float4(in_y - fy, in_x - fx, valid ? 1.0f : 0.0f, 0.0f);
    }
    __syncthreads();
    if (tid == 0) {
        int s = 0;
        #pragma unroll
        for (int w = 0; w < 16; ++w) s += sRed[w];
        sSlot = s;
    }
    __syncthreads();

    const float4* f4 = (const float4*)fm;
    float4* o4 = (float4*)out + (size_t)(b * NBOX + sSlot) * ITEMS;

    const int c = tid & (C4 - 1);   // loop-invariant channel group

    #pragma unroll
    for (int k = 0; k < 6; ++k) {
        const int i   = k * 512 + tid;
        const int pix = (k * 8) + (tid >> 6);   // == i >> 6

        const int4   id = sIdx[pix];
        const float4 w  = sW[pix];              // w.x=wy, w.y=wx, w.z=valid

        const float4 tl = __ldg(f4 + id.x + c);
        const float4 tr = __ldg(f4 + id.y + c);
        const float4 bl = __ldg(f4 + id.z + c);
        const float4 br = __ldg(f4 + id.w + c);

        float4 r;
        {
            float top, bot;
            top = tl.x + (tr.x - tl.x) * w.y; bot = bl.x + (br.x - bl.x) * w.y;
            r.x = (top + (bot - top) * w.x) * w.z;
            top = tl.y + (tr.y - tl.y) * w.y; bot = bl.y + (br.y - bl.y) * w.y;
            r.y = (top + (bot - top) * w.x) * w.z;
            top = tl.z + (tr.z - tl.z) * w.y; bot = bl.z + (br.z - bl.z) * w.y;
            r.z = (top + (bot - top) * w.x) * w.z;
            top = tl.w + (tr.w - tl.w) * w.y; bot = bl.w + (br.w - bl.w) * w.y;
            r.w = (top + (bot - top) * w.x) * w.z;
        }
        __stcs(o4 + i, r);
    }

    // tail: pixel 48, 64 items
    if (tid < C4) {
        const int4   id = sIdx[48];
        const float4 w  = sW[48];
        const float4 tl = __ldg(f4 + id.x + tid);
        const float4 tr = __ldg(f4 + id.y + tid);
        const float4 bl = __ldg(f4 + id.z + tid);
        const float4 br = __ldg(f4 + id.w + tid);
        float4 r;
        float top, bot;
        top = tl.x + (tr.x - tl.x) * w.y; bot = bl.x + (br.x - bl.x) * w.y;
        r.x = (top + (bot - top) * w.x) * w.z;
        top = tl.y + (tr.y - tl.y) * w.y; bot = bl.y + (br.y - bl.y) * w.y;
        r.y = (top + (bot - top) * w.x) * w.z;
        top = tl.z + (tr.z - tl.z) * w.y; bot = bl.z + (br.z - bl.z) * w.y;
        r.z = (top + (bot - top) * w.x) * w.z;
        top = tl.w + (tr.w - tl.w) * w.y; bot = bl.w + (br.w - bl.w) * w.y;
        r.w = (top + (bot - top) * w.x) * w.z;
        __stcs(o4 + 3072 + tid, r);
    }
}

// ---------------------------------------------------------------------------
// Launch: single fused kernel.
// ---------------------------------------------------------------------------
extern "C" void kernel_launch(void* const* d_in, const int* in_sizes, int n_in,
                              void* d_out, int out_size) {
    const float* boxes = (const float*)d_in[0];
    const float* fm0   = (const float*)d_in[1];
    const float* fm1   = (const float*)d_in[2];
    const float* fm2   = (const float*)d_in[3];
    const float* fm3   = (const float*)d_in[4];
    const int*   level = (const int*)  d_in[5];
    float*       out   = (float*)d_out;

    roi_kernel<<<BATCH * NBOX, 512>>>(boxes, fm0, fm1, fm2, fm3, level, out);
}